// round 1
// baseline (speedup 1.0000x reference)
#include <cuda_runtime.h>
#include <cuda_bf16.h>
#include <cub/cub.cuh>

// Problem constants (fixed shapes for this problem)
constexpr int QN = 16;      // query rows
constexpr int D  = 384;     // embedding dim
constexpr int NV = D / 4;   // float4 per row
constexpr int N  = 50000;   // corpus docs
constexpr int PT = 512;     // PAV threads per row-block
constexpr int TOTAL = QN * N;

// ---------------- static device scratch (no allocations allowed) ------------
__device__ unsigned long long g_keys[TOTAL];
__device__ unsigned long long g_keys_sorted[TOTAL];
__device__ double g_bsum[TOTAL];   // per-thread local PAV block sums
__device__ int    g_bcnt[TOTAL];
__device__ double g_fsum[TOTAL];   // final merged blocks (sum -> later mean)
__device__ int    g_fcnt[TOTAL];
__device__ int    g_fend[TOTAL];   // final block end positions
__device__ int    g_nblk[QN * PT];
__device__ unsigned char g_temp[48u << 20];  // cub radix sort temp storage

// ---------------- sims + key build ------------------------------------------
// One warp per doc: normalize q in smem once per block, compute 16 dots + self
// dot, write sims and 56-bit sort keys: [row:4][ord(sim):32][gidx:20].
__global__ __launch_bounds__(256) void sim_kernel(
    const float* __restrict__ qg, const float* __restrict__ cg,
    float* __restrict__ sims, unsigned long long* __restrict__ keys)
{
    __shared__ float4 qsh[QN * NV];   // 24 KB
    __shared__ float qinv[QN];
    int tid = threadIdx.x;

    for (int i = tid; i < QN * NV; i += 256)
        qsh[i] = reinterpret_cast<const float4*>(qg)[i];
    __syncthreads();
    if (tid < QN) {
        float ss = 0.f;
        const float4* row = qsh + tid * NV;
        #pragma unroll 8
        for (int j = 0; j < NV; j++) {
            float4 v = row[j];
            ss += v.x*v.x + v.y*v.y + v.z*v.z + v.w*v.w;
        }
        qinv[tid] = 1.0f / fmaxf(sqrtf(ss), 1e-12f);
    }
    __syncthreads();
    for (int i = tid; i < QN * NV; i += 256) {
        float s = qinv[i / NV];
        float4 v = qsh[i];
        v.x *= s; v.y *= s; v.z *= s; v.w *= s;
        qsh[i] = v;
    }
    __syncthreads();

    int warp = tid >> 5, lane = tid & 31;
    int doc = blockIdx.x * 8 + warp;
    if (doc >= N) return;

    const float4* cp = reinterpret_cast<const float4*>(cg + (size_t)doc * D);
    float4 cv[3];
    #pragma unroll
    for (int j = 0; j < 3; j++) cv[j] = cp[lane + 32 * j];

    float ss = 0.f;
    #pragma unroll
    for (int j = 0; j < 3; j++)
        ss += cv[j].x*cv[j].x + cv[j].y*cv[j].y + cv[j].z*cv[j].z + cv[j].w*cv[j].w;

    float acc[QN];
    #pragma unroll
    for (int r = 0; r < QN; r++) {
        float a = 0.f;
        #pragma unroll
        for (int j = 0; j < 3; j++) {
            float4 qv = qsh[r * NV + lane + 32 * j];
            a += qv.x*cv[j].x + qv.y*cv[j].y + qv.z*cv[j].z + qv.w*cv[j].w;
        }
        acc[r] = a;
    }
    #pragma unroll
    for (int o = 16; o; o >>= 1) {
        ss += __shfl_xor_sync(0xFFFFFFFFu, ss, o);
        #pragma unroll
        for (int r = 0; r < QN; r++)
            acc[r] += __shfl_xor_sync(0xFFFFFFFFu, acc[r], o);
    }
    if (lane == 0) {
        float cinv = 1.0f / fmaxf(sqrtf(ss), 1e-12f);
        #pragma unroll
        for (int r = 0; r < QN; r++) {
            float sim = acc[r] * cinv;
            int gi = r * N + doc;
            sims[gi] = sim;
            unsigned u = __float_as_uint(sim);
            unsigned ord = u ^ ((u & 0x80000000u) ? 0xFFFFFFFFu : 0x80000000u);
            keys[gi] = ((unsigned long long)r << 52) |
                       ((unsigned long long)ord << 20) |
                       (unsigned long long)gi;
        }
    }
}

// ---------------- PAV (isotonic, nonincreasing) + expand + scatter ----------
// One block per row. Keys are sorted ascending by sim => z = -10*sim sorted
// descending. y_i = z_i - (N - i). Chunk-local PAV in parallel (pooling
// violators in any order is confluent), then a serial block-level merge.
__device__ __forceinline__ float decode_z(unsigned long long k) {
    unsigned ordv = (unsigned)(k >> 20);
    unsigned bits = (ordv & 0x80000000u) ? (ordv ^ 0x80000000u) : ~ordv;
    return __uint_as_float(bits) * -10.0f;
}

__global__ __launch_bounds__(PT) void pav_kernel(
    const unsigned long long* __restrict__ keys, float* __restrict__ ranks)
{
    const int row = blockIdx.x;
    const int t = threadIdx.x;
    const int L = (N + PT - 1) / PT;
    const int base = row * N;
    const int lo = t * L;
    const int hi = min(N, lo + L);
    const int sb = base + lo;

    // Phase A: local PAV over [lo, hi)
    int nb = 0;
    for (int i = lo; i < hi; i++) {
        float z = decode_z(keys[base + i]);
        double cs = (double)z - (double)(N - i);
        int cc = 1;
        while (nb > 0) {
            double ps = g_bsum[sb + nb - 1];
            int pc = g_bcnt[sb + nb - 1];
            if (!(ps * (double)cc < cs * (double)pc)) break;  // merge while prev mean < cur mean
            cs += ps; cc += pc; nb--;
        }
        g_bsum[sb + nb] = cs; g_bcnt[sb + nb] = cc; nb++;
    }
    g_nblk[row * PT + t] = nb;
    __syncthreads();

    // Phase B: serial merge of all threads' block lists (block granularity)
    __shared__ int shB;
    if (t == 0) {
        int B = 0;
        const int fb = base;
        for (int tt = 0; tt < PT; tt++) {
            int nbt = g_nblk[row * PT + tt];
            int bb = base + tt * L;
            for (int b = 0; b < nbt; b++) {
                double cs = g_bsum[bb + b];
                int cc = g_bcnt[bb + b];
                while (B > 0) {
                    double ps = g_fsum[fb + B - 1];
                    int pc = g_fcnt[fb + B - 1];
                    if (!(ps * (double)cc < cs * (double)pc)) break;
                    cs += ps; cc += pc; B--;
                }
                g_fsum[fb + B] = cs; g_fcnt[fb + B] = cc; B++;
            }
        }
        int e = 0;
        for (int b = 0; b < B; b++) {
            e += g_fcnt[fb + b];
            g_fend[fb + b] = e;
            g_fsum[fb + b] = g_fsum[fb + b] / (double)g_fcnt[fb + b];  // -> mean
        }
        shB = B;
    }
    __syncthreads();

    // Phase C: expand dual, primal = z - mean(block), scatter via embedded idx
    const int B = shB;
    const int fb = base;
    for (int i = t; i < N; i += PT) {
        unsigned long long k = keys[base + i];
        float z = decode_z(k);
        int loB = 0, hiB = B;
        while (loB < hiB) {
            int mid = (loB + hiB) >> 1;
            if (g_fend[fb + mid] > i) hiB = mid; else loB = mid + 1;
        }
        double primal = (double)z - g_fsum[fb + loB];
        ranks[(unsigned)(k & 0xFFFFFu)] = (float)primal;
    }
}

// ---------------- launch -----------------------------------------------------
extern "C" void kernel_launch(void* const* d_in, const int* in_sizes, int n_in,
                              void* d_out, int out_size)
{
    const float* q = (const float*)d_in[0];
    const float* c = (const float*)d_in[1];
    float* out = (float*)d_out;
    float* sims = out;            // [QN*N]
    float* ranks = out + TOTAL;   // [QN*N]

    void *pk = nullptr, *pks = nullptr, *pt = nullptr;
    cudaGetSymbolAddress(&pk, g_keys);
    cudaGetSymbolAddress(&pks, g_keys_sorted);
    cudaGetSymbolAddress(&pt, g_temp);

    sim_kernel<<<(N + 7) / 8, 256>>>(q, c, sims, (unsigned long long*)pk);

    size_t tb = 0;
    cub::DeviceRadixSort::SortKeys((void*)nullptr, tb,
                                   (const unsigned long long*)pk,
                                   (unsigned long long*)pks,
                                   TOTAL, 0, 56);
    if (tb <= sizeof(g_temp)) {
        cub::DeviceRadixSort::SortKeys(pt, tb,
                                       (const unsigned long long*)pk,
                                       (unsigned long long*)pks,
                                       TOTAL, 0, 56);
    }

    pav_kernel<<<QN, PT>>>((const unsigned long long*)pks, ranks);
}

// round 2
// speedup vs baseline: 1.5216x; 1.5216x over previous
#include <cuda_runtime.h>
#include <cuda_bf16.h>
#include <cub/cub.cuh>

// Problem constants (fixed shapes)
constexpr int QN = 16;      // query rows
constexpr int D  = 384;     // embedding dim
constexpr int NV = D / 4;   // float4 per row
constexpr int N  = 50000;   // corpus docs
constexpr int PT = 512;     // PAV threads per row-block
constexpr int L  = (N + PT - 1) / PT;   // 98 elements per PAV thread
constexpr int TOTAL = QN * N;
constexpr int M1 = 16;      // lists merged per level-1 merger
constexpr int NM1 = PT / M1;            // 32 level-1 mergers
constexpr int M1CAP = M1 * L;           // max blocks per level-1 output list

// ---------------- static device scratch (no allocations allowed) ------------
__device__ unsigned g_k32[TOTAL];
__device__ unsigned g_k32s[TOTAL];
__device__ unsigned long long g_v64[TOTAL];
__device__ unsigned long long g_v64s[TOTAL];

__device__ double g_asum[TOTAL];            // phase-A per-thread lists
__device__ int    g_acnt[TOTAL];
__device__ int    g_anb[QN * PT];

__device__ double g_m1s[QN * NM1 * M1CAP];  // level-1 merged lists
__device__ int    g_m1c[QN * NM1 * M1CAP];
__device__ int    g_m1n[QN * NM1];

__device__ double g_fs[TOTAL];              // final blocks (means)
__device__ int    g_fc[TOTAL];
__device__ int    g_fe[TOTAL];              // final block end positions

__device__ unsigned char g_temp[48u << 20]; // cub temp storage

// ---------------- sims + key/value build ------------------------------------
// One warp per doc: normalized q tile in smem, 16 dots + self dot via shuffle.
__global__ __launch_bounds__(256) void sim_kernel(
    const float* __restrict__ qg, const float* __restrict__ cg,
    float* __restrict__ sims, unsigned* __restrict__ keys,
    unsigned long long* __restrict__ vals)
{
    __shared__ float4 qsh[QN * NV];   // 24 KB
    __shared__ float qinv[QN];
    int tid = threadIdx.x;

    for (int i = tid; i < QN * NV; i += 256)
        qsh[i] = reinterpret_cast<const float4*>(qg)[i];
    __syncthreads();
    if (tid < QN) {
        float ss = 0.f;
        const float4* row = qsh + tid * NV;
        #pragma unroll 8
        for (int j = 0; j < NV; j++) {
            float4 v = row[j];
            ss += v.x*v.x + v.y*v.y + v.z*v.z + v.w*v.w;
        }
        qinv[tid] = 1.0f / fmaxf(sqrtf(ss), 1e-12f);
    }
    __syncthreads();
    for (int i = tid; i < QN * NV; i += 256) {
        float s = qinv[i / NV];
        float4 v = qsh[i];
        v.x *= s; v.y *= s; v.z *= s; v.w *= s;
        qsh[i] = v;
    }
    __syncthreads();

    int warp = tid >> 5, lane = tid & 31;
    int doc = blockIdx.x * 8 + warp;
    if (doc >= N) return;

    const float4* cp = reinterpret_cast<const float4*>(cg + (size_t)doc * D);
    float4 cv[3];
    #pragma unroll
    for (int j = 0; j < 3; j++) cv[j] = cp[lane + 32 * j];

    float ss = 0.f;
    #pragma unroll
    for (int j = 0; j < 3; j++)
        ss += cv[j].x*cv[j].x + cv[j].y*cv[j].y + cv[j].z*cv[j].z + cv[j].w*cv[j].w;

    float acc[QN];
    #pragma unroll
    for (int r = 0; r < QN; r++) {
        float a = 0.f;
        #pragma unroll
        for (int j = 0; j < 3; j++) {
            float4 qv = qsh[r * NV + lane + 32 * j];
            a += qv.x*cv[j].x + qv.y*cv[j].y + qv.z*cv[j].z + qv.w*cv[j].w;
        }
        acc[r] = a;
    }
    #pragma unroll
    for (int o = 16; o; o >>= 1) {
        ss += __shfl_xor_sync(0xFFFFFFFFu, ss, o);
        #pragma unroll
        for (int r = 0; r < QN; r++)
            acc[r] += __shfl_xor_sync(0xFFFFFFFFu, acc[r], o);
    }
    if (lane == 0) {
        float cinv = 1.0f / fmaxf(sqrtf(ss), 1e-12f);
        #pragma unroll
        for (int r = 0; r < QN; r++) {
            float sim = acc[r] * cinv;
            int gi = r * N + doc;
            sims[gi] = sim;
            unsigned u = __float_as_uint(sim);
            unsigned ord = u ^ ((u & 0x80000000u) ? 0xFFFFFFFFu : 0x80000000u);
            keys[gi] = ((unsigned)r << 28) | (ord >> 4);
            vals[gi] = ((unsigned long long)u << 32) | (unsigned long long)gi;
        }
    }
}

// ---------------- PAV (isotonic, nonincreasing) + expand + scatter ----------
// One block per row. Sorted vals carry [sim bits:32][gidx:20]; ascending sim
// order == descending z order (z = -10*sim). y_i = z_i - (N - i).
// Phase A: chunk-local PAV (local-memory stack). Phase B: 32-way then 1-way
// list merge (pooling violators in any order is confluent). Phase C: expand.
__global__ __launch_bounds__(PT) void pav_kernel(
    const unsigned long long* __restrict__ vals, float* __restrict__ ranks)
{
    const int row = blockIdx.x;
    const int t = threadIdx.x;
    const int base = row * N;
    const int lo = t * L;
    const int hi = min(N, lo + L);

    // Phase A: local PAV over [lo, hi), stack in thread-local memory
    double ls[L];
    int    lc[L];
    int nb = 0;
    for (int i = lo; i < hi; i++) {
        unsigned long long v = vals[base + i];
        float sim = __uint_as_float((unsigned)(v >> 32));
        double cs = (double)(sim * -10.0f) - (double)(N - i);
        int cc = 1;
        while (nb > 0 && ls[nb - 1] * (double)cc < cs * (double)lc[nb - 1]) {
            cs += ls[nb - 1]; cc += lc[nb - 1]; nb--;
        }
        ls[nb] = cs; lc[nb] = cc; nb++;
    }
    for (int b = 0; b < nb; b++) {
        g_asum[base + lo + b] = ls[b];
        g_acnt[base + lo + b] = lc[b];
    }
    g_anb[row * PT + t] = nb;
    __syncthreads();

    // Phase B1: 32 mergers, each merges 16 consecutive lists
    if (t < NM1) {
        const int ob = (row * NM1 + t) * M1CAP;
        int B = 0;
        for (int tt = t * M1; tt < t * M1 + M1; tt++) {
            int nbt = g_anb[row * PT + tt];
            int bb = base + tt * L;
            for (int b = 0; b < nbt; b++) {
                double cs = g_asum[bb + b];
                int cc = g_acnt[bb + b];
                while (B > 0 && g_m1s[ob + B - 1] * (double)cc < cs * (double)g_m1c[ob + B - 1]) {
                    cs += g_m1s[ob + B - 1]; cc += g_m1c[ob + B - 1]; B--;
                }
                g_m1s[ob + B] = cs; g_m1c[ob + B] = cc; B++;
            }
        }
        g_m1n[row * NM1 + t] = B;
    }
    __syncthreads();

    // Phase B2: final merge of 32 lists, compute ends + means
    __shared__ int shB;
    if (t == 0) {
        int B = 0;
        for (int m = 0; m < NM1; m++) {
            int nm = g_m1n[row * NM1 + m];
            const int ob = (row * NM1 + m) * M1CAP;
            for (int b = 0; b < nm; b++) {
                double cs = g_m1s[ob + b];
                int cc = g_m1c[ob + b];
                while (B > 0 && g_fs[base + B - 1] * (double)cc < cs * (double)g_fc[base + B - 1]) {
                    cs += g_fs[base + B - 1]; cc += g_fc[base + B - 1]; B--;
                }
                g_fs[base + B] = cs; g_fc[base + B] = cc; B++;
            }
        }
        int e = 0;
        for (int b = 0; b < B; b++) {
            e += g_fc[base + b];
            g_fe[base + b] = e;
            g_fs[base + b] = g_fs[base + b] / (double)g_fc[base + b];  // -> mean
        }
        shB = B;
    }
    __syncthreads();

    // Phase C: primal = z - mean(block), scatter via embedded gidx
    const int B = shB;
    for (int i = t; i < N; i += PT) {
        unsigned long long v = vals[base + i];
        float sim = __uint_as_float((unsigned)(v >> 32));
        float z = sim * -10.0f;
        int loB = 0, hiB = B;
        while (loB < hiB) {
            int mid = (loB + hiB) >> 1;
            if (g_fe[base + mid] > i) hiB = mid; else loB = mid + 1;
        }
        double primal = (double)z - g_fs[base + loB];
        ranks[(unsigned)(v & 0xFFFFFu)] = (float)primal;
    }
}

// ---------------- launch -----------------------------------------------------
extern "C" void kernel_launch(void* const* d_in, const int* in_sizes, int n_in,
                              void* d_out, int out_size)
{
    const float* q = (const float*)d_in[0];
    const float* c = (const float*)d_in[1];
    float* out = (float*)d_out;
    float* sims = out;            // [QN*N]
    float* ranks = out + TOTAL;   // [QN*N]

    void *pk = nullptr, *pks = nullptr, *pv = nullptr, *pvs = nullptr, *pt = nullptr;
    cudaGetSymbolAddress(&pk, g_k32);
    cudaGetSymbolAddress(&pks, g_k32s);
    cudaGetSymbolAddress(&pv, g_v64);
    cudaGetSymbolAddress(&pvs, g_v64s);
    cudaGetSymbolAddress(&pt, g_temp);

    sim_kernel<<<(N + 7) / 8, 256>>>(q, c, sims, (unsigned*)pk,
                                     (unsigned long long*)pv);

    size_t tb = 0;
    cub::DeviceRadixSort::SortPairs((void*)nullptr, tb,
                                    (const unsigned*)pk, (unsigned*)pks,
                                    (const unsigned long long*)pv,
                                    (unsigned long long*)pvs,
                                    TOTAL, 0, 32);
    if (tb <= sizeof(g_temp)) {
        cub::DeviceRadixSort::SortPairs(pt, tb,
                                        (const unsigned*)pk, (unsigned*)pks,
                                        (const unsigned long long*)pv,
                                        (unsigned long long*)pvs,
                                        TOTAL, 0, 32);
    }

    pav_kernel<<<QN, PT>>>((const unsigned long long*)pvs, ranks);
}

// round 4
// speedup vs baseline: 2.3320x; 1.5327x over previous
#include <cuda_runtime.h>
#include <cuda_bf16.h>
#include <cub/cub.cuh>

// Problem constants (fixed shapes)
constexpr int QN = 16;      // query rows
constexpr int D  = 384;     // embedding dim
constexpr int NV = D / 4;   // float4 per row
constexpr int N  = 50000;   // corpus docs
constexpr int TOTAL = QN * N;

// PAV decomposition
constexpr int TPR  = 1280;            // PAV threads per row
constexpr int LL   = 40;              // elements per PAV thread (1280*40=51200>=N)
constexpr int TBA  = 128;             // threads per pavA block
constexpr int NBA  = TPR / TBA;       // 10 pavA blocks per row
constexpr int CHUNK = TBA * LL;       // 5120 elements per pavA block (40KB smem)
constexpr int NM   = 40;              // level-1 mergers per row
constexpr int MW   = TPR / NM;        // 32 lists per merger
constexpr int MCAP = MW * LL;         // 1280 max blocks per merger output
constexpr int NBC  = 10;              // pavC blocks per row
constexpr int CC   = N / NBC;         // 5000 elements per pavC block

// ---------------- static device scratch (no allocations allowed) ------------
__device__ unsigned g_k32[TOTAL];
__device__ unsigned g_k32s[TOTAL];
__device__ unsigned long long g_v64[TOTAL];
__device__ unsigned long long g_v64s[TOTAL];

__device__ double g_asum[QN * TPR * LL];   // phase-A per-thread lists
__device__ int    g_acnt[QN * TPR * LL];
__device__ int    g_anb[QN * TPR];

__device__ double g_m1s[QN * NM * MCAP];   // level-1 merged lists
__device__ int    g_m1c[QN * NM * MCAP];
__device__ int    g_m1n[QN * NM];

__device__ double g_fs[TOTAL];             // final block means
__device__ int    g_fc[TOTAL];
__device__ int    g_fe[TOTAL];             // final block end positions
__device__ int    g_B[QN];                 // final block counts

__device__ unsigned char g_temp[48u << 20]; // cub temp storage

// ---------------- sims + key/value build ------------------------------------
// Persistent blocks: stage+normalize q once, then warps loop over docs.
__global__ __launch_bounds__(256) void sim_kernel(
    const float* __restrict__ qg, const float* __restrict__ cg,
    float* __restrict__ sims, unsigned* __restrict__ keys,
    unsigned long long* __restrict__ vals)
{
    __shared__ float4 qsh[QN * NV];   // 24 KB
    __shared__ float qinv[QN];
    int tid = threadIdx.x;

    for (int i = tid; i < QN * NV; i += 256)
        qsh[i] = reinterpret_cast<const float4*>(qg)[i];
    __syncthreads();
    if (tid < QN) {
        float ss = 0.f;
        const float4* row = qsh + tid * NV;
        #pragma unroll 8
        for (int j = 0; j < NV; j++) {
            float4 v = row[j];
            ss += v.x*v.x + v.y*v.y + v.z*v.z + v.w*v.w;
        }
        qinv[tid] = 1.0f / fmaxf(sqrtf(ss), 1e-12f);
    }
    __syncthreads();
    for (int i = tid; i < QN * NV; i += 256) {
        float s = qinv[i / NV];
        float4 v = qsh[i];
        v.x *= s; v.y *= s; v.z *= s; v.w *= s;
        qsh[i] = v;
    }
    __syncthreads();

    const int warp = tid >> 5, lane = tid & 31;
    const int gw = blockIdx.x * 8 + warp;        // global warp id, 1600 warps
    const int NW = gridDim.x * 8;

    for (int doc = gw; doc < N; doc += NW) {
        const float4* cp = reinterpret_cast<const float4*>(cg + (size_t)doc * D);
        float4 cv[3];
        #pragma unroll
        for (int j = 0; j < 3; j++) cv[j] = cp[lane + 32 * j];

        float ss = 0.f;
        #pragma unroll
        for (int j = 0; j < 3; j++)
            ss += cv[j].x*cv[j].x + cv[j].y*cv[j].y + cv[j].z*cv[j].z + cv[j].w*cv[j].w;

        float acc[QN];
        #pragma unroll
        for (int r = 0; r < QN; r++) {
            float a = 0.f;
            #pragma unroll
            for (int j = 0; j < 3; j++) {
                float4 qv = qsh[r * NV + lane + 32 * j];
                a += qv.x*cv[j].x + qv.y*cv[j].y + qv.z*cv[j].z + qv.w*cv[j].w;
            }
            acc[r] = a;
        }
        #pragma unroll
        for (int o = 16; o; o >>= 1) {
            ss += __shfl_xor_sync(0xFFFFFFFFu, ss, o);
            #pragma unroll
            for (int r = 0; r < QN; r++)
                acc[r] += __shfl_xor_sync(0xFFFFFFFFu, acc[r], o);
        }
        if (lane == 0) {
            float cinv = 1.0f / fmaxf(sqrtf(ss), 1e-12f);
            #pragma unroll
            for (int r = 0; r < QN; r++) {
                float sim = acc[r] * cinv;
                int gi = r * N + doc;
                sims[gi] = sim;
                unsigned u = __float_as_uint(sim);
                unsigned ord = u ^ ((u & 0x80000000u) ? 0xFFFFFFFFu : 0x80000000u);
                keys[gi] = ((unsigned)r << 16) | (ord >> 16);   // 20-bit key
                vals[gi] = ((unsigned long long)u << 32) | (unsigned long long)gi;
            }
        }
    }
}

// ---------------- PAV phase A: chunk-local PAV (160 blocks) ------------------
// Sorted vals carry [sim bits:32][gidx:20]; ascending sim == descending z
// (z = -10*sim). y_i = z_i - (N - i). Pooling violators in any order is
// confluent, so chunk-local PAV followed by list merges is exact.
__global__ __launch_bounds__(TBA) void pavA_kernel(
    const unsigned long long* __restrict__ vals)
{
    __shared__ unsigned long long sh[CHUNK];   // 40 KB
    const int row = blockIdx.y;
    const int bi  = blockIdx.x;
    const int t   = threadIdx.x;
    const int blo = bi * CHUNK;                       // row-local chunk start
    const int cnt = min(CHUNK, N - blo);              // may be partial

    for (int i = t; i < cnt; i += TBA)
        sh[i] = vals[row * N + blo + i];
    __syncthreads();

    const int lo = t * LL;
    const int hi = min(cnt, lo + LL);

    double ls[LL];
    int    lc[LL];
    int nb = 0;
    for (int i = lo; i < hi; i++) {
        unsigned long long v = sh[i];
        float sim = __uint_as_float((unsigned)(v >> 32));
        int gpos = blo + i;                            // row-local sorted pos
        double cs = (double)(sim * -10.0f) - (double)(N - gpos);
        int cc = 1;
        while (nb > 0 && ls[nb - 1] * (double)cc < cs * (double)lc[nb - 1]) {
            cs += ls[nb - 1]; cc += lc[nb - 1]; nb--;
        }
        ls[nb] = cs; lc[nb] = cc; nb++;
    }
    const int gt = bi * TBA + t;                       // row-local thread id
    const int ob = (row * TPR + gt) * LL;
    for (int b = 0; b < nb; b++) {
        g_asum[ob + b] = ls[b];
        g_acnt[ob + b] = lc[b];
    }
    g_anb[row * TPR + gt] = nb;
}

// ---------------- PAV phase B: 2-level list merge (16 small blocks) ----------
__global__ __launch_bounds__(64) void pavB_kernel()
{
    const int row = blockIdx.x;
    const int t = threadIdx.x;

    // Level 1: 40 mergers, each merges 32 consecutive thread lists
    if (t < NM) {
        const int ob = (row * NM + t) * MCAP;
        int B = 0;
        for (int tt = t * MW; tt < t * MW + MW; tt++) {
            int nbt = g_anb[row * TPR + tt];
            const int bb = (row * TPR + tt) * LL;
            for (int b = 0; b < nbt; b++) {
                double cs = g_asum[bb + b];
                int cc = g_acnt[bb + b];
                while (B > 0 && g_m1s[ob + B - 1] * (double)cc < cs * (double)g_m1c[ob + B - 1]) {
                    cs += g_m1s[ob + B - 1]; cc += g_m1c[ob + B - 1]; B--;
                }
                g_m1s[ob + B] = cs; g_m1c[ob + B] = cc; B++;
            }
        }
        g_m1n[row * NM + t] = B;
    }
    __syncthreads();

    // Level 2: merge 40 lists, compute ends + means
    if (t == 0) {
        const int fb = row * N;
        int B = 0;
        for (int m = 0; m < NM; m++) {
            int nm = g_m1n[row * NM + m];
            const int ob = (row * NM + m) * MCAP;
            for (int b = 0; b < nm; b++) {
                double cs = g_m1s[ob + b];
                int cc = g_m1c[ob + b];
                while (B > 0 && g_fs[fb + B - 1] * (double)cc < cs * (double)g_fc[fb + B - 1]) {
                    cs += g_fs[fb + B - 1]; cc += g_fc[fb + B - 1]; B--;
                }
                g_fs[fb + B] = cs; g_fc[fb + B] = cc; B++;
            }
        }
        int e = 0;
        for (int b = 0; b < B; b++) {
            e += g_fc[fb + b];
            g_fe[fb + b] = e;
            g_fs[fb + b] = g_fs[fb + b] / (double)g_fc[fb + b];  // -> mean
        }
        g_B[row] = B;
    }
}

// ---------------- PAV phase C: expand + scatter (160 blocks) -----------------
__global__ __launch_bounds__(256) void pavC_kernel(
    const unsigned long long* __restrict__ vals, float* __restrict__ ranks)
{
    const int row = blockIdx.y;
    const int bi  = blockIdx.x;
    const int t   = threadIdx.x;
    const int blo = bi * CC;
    const int B   = g_B[row];
    const int fb  = row * N;

    for (int i = blo + t; i < blo + CC; i += 256) {
        unsigned long long v = vals[row * N + i];
        float sim = __uint_as_float((unsigned)(v >> 32));
        float z = sim * -10.0f;
        int loB = 0, hiB = B;
        while (loB < hiB) {
            int mid = (loB + hiB) >> 1;
            if (g_fe[fb + mid] > i) hiB = mid; else loB = mid + 1;
        }
        double primal = (double)z - g_fs[fb + loB];
        ranks[(unsigned)(v & 0xFFFFFu)] = (float)primal;
    }
}

// ---------------- launch -----------------------------------------------------
extern "C" void kernel_launch(void* const* d_in, const int* in_sizes, int n_in,
                              void* d_out, int out_size)
{
    const float* q = (const float*)d_in[0];
    const float* c = (const float*)d_in[1];
    float* out = (float*)d_out;
    float* sims = out;            // [QN*N]
    float* ranks = out + TOTAL;   // [QN*N]

    void *pk = nullptr, *pks = nullptr, *pv = nullptr, *pvs = nullptr, *pt = nullptr;
    cudaGetSymbolAddress(&pk, g_k32);
    cudaGetSymbolAddress(&pks, g_k32s);
    cudaGetSymbolAddress(&pv, g_v64);
    cudaGetSymbolAddress(&pvs, g_v64s);
    cudaGetSymbolAddress(&pt, g_temp);

    sim_kernel<<<200, 256>>>(q, c, sims, (unsigned*)pk,
                             (unsigned long long*)pv);

    size_t tb = 0;
    cub::DeviceRadixSort::SortPairs((void*)nullptr, tb,
                                    (const unsigned*)pk, (unsigned*)pks,
                                    (const unsigned long long*)pv,
                                    (unsigned long long*)pvs,
                                    TOTAL, 0, 20);
    if (tb <= sizeof(g_temp)) {
        cub::DeviceRadixSort::SortPairs(pt, tb,
                                        (const unsigned*)pk, (unsigned*)pks,
                                        (const unsigned long long*)pv,
                                        (unsigned long long*)pvs,
                                        TOTAL, 0, 20);
    }

    dim3 gA(NBA, QN);
    pavA_kernel<<<gA, TBA>>>((const unsigned long long*)pvs);
    pavB_kernel<<<QN, 64>>>();
    dim3 gC(NBC, QN);
    pavC_kernel<<<gC, 256>>>((const unsigned long long*)pvs, ranks);
}